// round 10
// baseline (speedup 1.0000x reference)
#include <cuda_runtime.h>
#include <cuda_bf16.h>
#include <cstdint>

#define SEQ 4096
#define DIM 1024
#define NH  16
#define HS  64

// ---------------- device scratch (no allocation allowed) -------------------
__device__ __nv_bfloat16 g_xh[SEQ * DIM],  g_xl[SEQ * DIM];
__device__ __nv_bfloat16 g_ah[SEQ * DIM],  g_al[SEQ * DIM];
__device__ __nv_bfloat16 g_wqh[DIM * DIM], g_wql[DIM * DIM];
__device__ __nv_bfloat16 g_wkh[DIM * DIM], g_wkl[DIM * DIM];
__device__ __nv_bfloat16 g_wvh[DIM * DIM], g_wvl[DIM * DIM];
__device__ __nv_bfloat16 g_woh[DIM * DIM], g_wol[DIM * DIM];
__device__ __nv_bfloat16 g_qh[NH * SEQ * HS], g_ql[NH * SEQ * HS];
__device__ __nv_bfloat16 g_kh[NH * SEQ * HS], g_kl[NH * SEQ * HS];
__device__ __nv_bfloat16 g_vh[NH * SEQ * HS], g_vl[NH * SEQ * HS];

// ---------------- helpers ---------------------------------------------------
__device__ __forceinline__ uint32_t su32(const void* p) {
    uint32_t a;
    asm("{ .reg .u64 t; cvta.to.shared.u64 t, %1; cvt.u32.u64 %0, t; }"
        : "=r"(a) : "l"(p));
    return a;
}
__device__ __forceinline__ void cpa16(uint32_t d, const void* s) {
    asm volatile("cp.async.cg.shared.global [%0], [%1], 16;" :: "r"(d), "l"(s));
}
#define CP_COMMIT() asm volatile("cp.async.commit_group;" ::: "memory")
#define CP_WAIT(n)  asm volatile("cp.async.wait_group %0;" :: "n"(n) : "memory")

__device__ __forceinline__ void ldsm4(uint32_t (&r)[4], uint32_t a) {
    asm volatile("ldmatrix.sync.aligned.m8n8.x4.shared.b16 {%0,%1,%2,%3}, [%4];"
        : "=r"(r[0]), "=r"(r[1]), "=r"(r[2]), "=r"(r[3]) : "r"(a));
}
__device__ __forceinline__ void ldsm4t(uint32_t (&r)[4], uint32_t a) {
    asm volatile("ldmatrix.sync.aligned.m8n8.x4.trans.shared.b16 {%0,%1,%2,%3}, [%4];"
        : "=r"(r[0]), "=r"(r[1]), "=r"(r[2]), "=r"(r[3]) : "r"(a));
}
__device__ __forceinline__ void mma16816(float (&c)[4],
                                         uint32_t a0, uint32_t a1, uint32_t a2, uint32_t a3,
                                         uint32_t b0, uint32_t b1) {
    asm volatile(
        "mma.sync.aligned.m16n8k16.row.col.f32.bf16.bf16.f32 "
        "{%0,%1,%2,%3}, {%4,%5,%6,%7}, {%8,%9}, {%0,%1,%2,%3};"
        : "+f"(c[0]), "+f"(c[1]), "+f"(c[2]), "+f"(c[3])
        : "r"(a0), "r"(a1), "r"(a2), "r"(a3), "r"(b0), "r"(b1));
}
__device__ __forceinline__ uint32_t pk(__nv_bfloat16 a, __nv_bfloat16 b) {
    __nv_bfloat162 t(a, b);
    return *reinterpret_cast<uint32_t*>(&t);
}

// ---------------------------------------------------------------------------
// fp32 -> bf16 hi/lo split
// ---------------------------------------------------------------------------
__global__ void conv_split(const float* __restrict__ s,
                           __nv_bfloat16* __restrict__ hi,
                           __nv_bfloat16* __restrict__ lo, int n4)
{
    int i = blockIdx.x * blockDim.x + threadIdx.x;
    if (i >= n4) return;
    float4 v = ((const float4*)s)[i];
    __nv_bfloat16 hx = __float2bfloat16(v.x), hy = __float2bfloat16(v.y);
    __nv_bfloat16 hz = __float2bfloat16(v.z), hw = __float2bfloat16(v.w);
    __nv_bfloat16 lx = __float2bfloat16(v.x - __bfloat162float(hx));
    __nv_bfloat16 ly = __float2bfloat16(v.y - __bfloat162float(hy));
    __nv_bfloat16 lz = __float2bfloat16(v.z - __bfloat162float(hz));
    __nv_bfloat16 lw = __float2bfloat16(v.w - __bfloat162float(hw));
    ((__nv_bfloat162*)hi)[2 * i]     = __nv_bfloat162(hx, hy);
    ((__nv_bfloat162*)hi)[2 * i + 1] = __nv_bfloat162(hz, hw);
    ((__nv_bfloat162*)lo)[2 * i]     = __nv_bfloat162(lx, ly);
    ((__nv_bfloat162*)lo)[2 * i + 1] = __nv_bfloat162(lz, lw);
}

// ---------------------------------------------------------------------------
// mma.sync GEMM with ldmatrix feed.  CTA 128x128, 8 warps (4m x 2n),
// warp tile 32x64, BK=32, cp.async double buffer.  MODE 1 output is
// pre-scaled by `scale` (used to fold 1/sqrt(hs) into Q).
// ---------------------------------------------------------------------------
#define GSTR_B 80
#define GPLANE (128 * GSTR_B)
#define GSTAGE (4 * GPLANE)
#define GEMM_SMEM (2 * GSTAGE)

template <int MODE>
__global__ __launch_bounds__(256, 2)
void gemm_mma(const __nv_bfloat16* __restrict__ Ah, const __nv_bfloat16* __restrict__ Al,
              const __nv_bfloat16* __restrict__ Bh, const __nv_bfloat16* __restrict__ Bl,
              const float* __restrict__ bias, float scale,
              __nv_bfloat16* __restrict__ Chi, __nv_bfloat16* __restrict__ Clo,
              float* __restrict__ Cf)
{
    extern __shared__ char smc[];
    const uint32_t smb = su32(smc);
    const int tid = threadIdx.x, lane = tid & 31, wid = tid >> 5;
    const int wm = wid & 3, wn = wid >> 2;
    const int bm = blockIdx.y * 128, bn = blockIdx.x * 128;

    const int lg = lane >> 3, lr8 = lane & 7;
    const uint32_t offG = (uint32_t)((lr8 + (lg & 1) * 8) * GSTR_B + (lg >> 1) * 16);

    const __nv_bfloat16* gp[4] = {Ah, Al, Bh, Bl};
    const int gbase[4] = {bm, bm, bn, bn};

    float c[2][8][4];
#pragma unroll
    for (int mt = 0; mt < 2; mt++)
#pragma unroll
        for (int nt = 0; nt < 8; nt++)
#pragma unroll
            for (int e = 0; e < 4; e++) c[mt][nt][e] = 0.f;

    auto issue = [&](int s) {
        const uint32_t sb = smb + (s & 1) * GSTAGE;
        const int k0 = s * 32;
#pragma unroll
        for (int p = 0; p < 4; p++)
#pragma unroll
            for (int i = 0; i < 2; i++) {
                const int id = tid + i * 256;
                const int row = id >> 2, ch = id & 3;
                cpa16(sb + p * GPLANE + row * GSTR_B + ch * 16,
                      gp[p] + (size_t)(gbase[p] + row) * DIM + k0 + ch * 8);
            }
        CP_COMMIT();
    };

    issue(0);
    const int NS = DIM / 32;
    for (int s = 0; s < NS; s++) {
        if (s + 1 < NS) { issue(s + 1); CP_WAIT(1); }
        else            { CP_WAIT(0); }
        __syncthreads();
        const uint32_t sb = smb + (s & 1) * GSTAGE;
        const uint32_t aH = sb, aL = sb + GPLANE, bH = sb + 2 * GPLANE, bL = sb + 3 * GPLANE;
#pragma unroll
        for (int kq = 0; kq < 2; kq++) {
            uint32_t afh[2][4], afl[2][4];
#pragma unroll
            for (int mt = 0; mt < 2; mt++) {
                const uint32_t rb = (uint32_t)((wm * 32 + mt * 16) * GSTR_B + kq * 32) + offG;
                ldsm4(afh[mt], aH + rb);
                ldsm4(afl[mt], aL + rb);
            }
#pragma unroll
            for (int ng = 0; ng < 4; ng++) {
                const uint32_t rb = (uint32_t)((wn * 64 + ng * 16) * GSTR_B + kq * 32) + offG;
                uint32_t bh[4], bl[4];
                ldsm4(bh, bH + rb);
                ldsm4(bl, bL + rb);
#pragma unroll
                for (int mt = 0; mt < 2; mt++) {
                    mma16816(c[mt][2*ng],   afh[mt][0],afh[mt][1],afh[mt][2],afh[mt][3], bh[0], bh[2]);
                    mma16816(c[mt][2*ng],   afh[mt][0],afh[mt][1],afh[mt][2],afh[mt][3], bl[0], bl[2]);
                    mma16816(c[mt][2*ng],   afl[mt][0],afl[mt][1],afl[mt][2],afl[mt][3], bh[0], bh[2]);
                    mma16816(c[mt][2*ng+1], afh[mt][0],afh[mt][1],afh[mt][2],afh[mt][3], bh[1], bh[3]);
                    mma16816(c[mt][2*ng+1], afh[mt][0],afh[mt][1],afh[mt][2],afh[mt][3], bl[1], bl[3]);
                    mma16816(c[mt][2*ng+1], afl[mt][0],afl[mt][1],afl[mt][2],afl[mt][3], bh[1], bh[3]);
                }
            }
        }
        __syncthreads();
    }

#pragma unroll
    for (int mt = 0; mt < 2; mt++)
#pragma unroll
        for (int nt = 0; nt < 8; nt++) {
            const int col = bn + wn * 64 + nt * 8 + (lane & 3) * 2;
            const float b0 = bias[col], b1 = bias[col + 1];
#pragma unroll
            for (int h = 0; h < 2; h++) {
                const int row = bm + wm * 32 + mt * 16 + (lane >> 2) + h * 8;
                float v0 = c[mt][nt][h * 2 + 0] + b0;
                float v1 = c[mt][nt][h * 2 + 1] + b1;
                if (MODE == 1) {
                    v0 *= scale; v1 *= scale;
                    const int head = col >> 6, off = col & 63;
                    const size_t idx = ((size_t)head * SEQ + row) * HS + off;
                    __nv_bfloat16 h0 = __float2bfloat16(v0), h1 = __float2bfloat16(v1);
                    __nv_bfloat16 l0 = __float2bfloat16(v0 - __bfloat162float(h0));
                    __nv_bfloat16 l1 = __float2bfloat16(v1 - __bfloat162float(h1));
                    *(uint32_t*)&Chi[idx] = pk(h0, h1);
                    *(uint32_t*)&Clo[idx] = pk(l0, l1);
                } else {
                    *(float2*)&Cf[(size_t)row * DIM + col] = make_float2(v0, v1);
                }
            }
        }
}

// ---------------------------------------------------------------------------
// Flash attention: q-tile 128 (256 thr, 8 warps x 16 q rows), k-tile 64,
// ldmatrix feed, ldmatrix.trans V, double-buffered cp.async K/V pipeline.
// Q pre-scaled by 1/sqrt(hs) in the projection.
// ---------------------------------------------------------------------------
#define APAD_B  144
#define APLANE  (64 * APAD_B)
#define AST     (4 * APLANE)
#define ATT_SMEM (2 * AST)

__global__ __launch_bounds__(256, 2)
void attn_mma()
{
    extern __shared__ char smc[];
    const uint32_t smb = su32(smc);
    const int tid = threadIdx.x, lane = tid & 31, wid = tid >> 5;
    const int head = blockIdx.y;
    const int qt   = (SEQ / 128 - 1) - blockIdx.x;   // heavy CTAs first
    const int ktmax = 2 * qt + 1;

    const int lg = lane >> 3, lr8 = lane & 7;
    const uint32_t offA = (uint32_t)((lr8 + (lg & 1) * 8) * APAD_B + (lg >> 1) * 16);
    const uint32_t offV = (uint32_t)((lr8 + (lg >> 1) * 8) * APAD_B + (lg & 1) * 16);

    const size_t hb = (size_t)head * SEQ * HS;
    const __nv_bfloat16* Qhg = g_qh + hb + (size_t)qt * 128 * HS;
    const __nv_bfloat16* Qlg = g_ql + hb + (size_t)qt * 128 * HS;
    const __nv_bfloat16* Khg = g_kh + hb;
    const __nv_bfloat16* Klg = g_kl + hb;
    const __nv_bfloat16* Vhg = g_vh + hb;
    const __nv_bfloat16* Vlg = g_vl + hb;

    // Q (128 rows x 64) -> stage0's 4 planes: Qh rows 0-63 -> p0, 64-127 -> p1,
    // Ql -> p2/p3.  Extract fragments, then the space becomes K/V stage 0.
#pragma unroll
    for (int i = 0; i < 4; i++) {
        const int id = tid + i * 256;            // 0..1023
        const int row = id >> 3, ch = id & 7;
        const uint32_t da = (row & 63) * APAD_B + ch * 16;
        const uint32_t ph = (uint32_t)(row >> 6) * APLANE;
        cpa16(smb + ph + da,               Qhg + row * HS + ch * 8);
        cpa16(smb + (2 * APLANE) + ph + da, Qlg + row * HS + ch * 8);
    }
    CP_COMMIT(); CP_WAIT(0);
    __syncthreads();
    uint32_t qfh[4][4], qfl[4][4];
    {
        const uint32_t ph = (uint32_t)(wid >> 2) * APLANE;
        const uint32_t rbase = (uint32_t)((wid & 3) * 16 * APAD_B);
#pragma unroll
        for (int kq = 0; kq < 4; kq++) {
            const uint32_t rb = rbase + kq * 32 + offA;
            ldsm4(qfh[kq], smb + ph + rb);
            ldsm4(qfl[kq], smb + 2 * APLANE + ph + rb);
        }
    }
    __syncthreads();

    auto issue = [&](int kt) {
        const uint32_t sb = smb + (kt & 1) * AST;
#pragma unroll
        for (int i = 0; i < 2; i++) {
            const int id = tid + i * 256;        // 0..511
            const int row = id >> 3, ch = id & 7;
            const size_t src = (size_t)(kt * 64 + row) * HS + ch * 8;
            const uint32_t da = row * APAD_B + ch * 16;
            cpa16(sb + 0 * APLANE + da, Khg + src);
            cpa16(sb + 1 * APLANE + da, Klg + src);
            cpa16(sb + 2 * APLANE + da, Vhg + src);
            cpa16(sb + 3 * APLANE + da, Vlg + src);
        }
        CP_COMMIT();
    };

    issue(0);
    issue(1);   // ktmax >= 1 always

    float o[8][4];
#pragma unroll
    for (int nt = 0; nt < 8; nt++)
#pragma unroll
        for (int e = 0; e < 4; e++) o[nt][e] = 0.f;
    float m_i[2] = {-1e30f, -1e30f}, l_i[2] = {0.f, 0.f};

    for (int kt = 0; kt <= ktmax; kt++) {
        if (kt < ktmax) CP_WAIT(1); else CP_WAIT(0);
        __syncthreads();
        const uint32_t sb  = smb + (kt & 1) * AST;
        const uint32_t sKh = sb, sKl = sb + APLANE, sVh = sb + 2 * APLANE, sVl = sb + 3 * APLANE;

        float s[8][4];
#pragma unroll
        for (int nt = 0; nt < 8; nt++)
#pragma unroll
            for (int e = 0; e < 4; e++) s[nt][e] = 0.f;

#pragma unroll
        for (int kq = 0; kq < 4; kq++) {
#pragma unroll
            for (int ng = 0; ng < 4; ng++) {
                const uint32_t rb = (uint32_t)(ng * 16 * APAD_B + kq * 32) + offA;
                uint32_t kbh[4], kbl[4];
                ldsm4(kbh, sKh + rb);
                ldsm4(kbl, sKl + rb);
                mma16816(s[2*ng],   qfh[kq][0],qfh[kq][1],qfh[kq][2],qfh[kq][3], kbh[0], kbh[2]);
                mma16816(s[2*ng],   qfh[kq][0],qfh[kq][1],qfh[kq][2],qfh[kq][3], kbl[0], kbl[2]);
                mma16816(s[2*ng],   qfl[kq][0],qfl[kq][1],qfl[kq][2],qfl[kq][3], kbh[0], kbh[2]);
                mma16816(s[2*ng+1], qfh[kq][0],qfh[kq][1],qfh[kq][2],qfh[kq][3], kbh[1], kbh[3]);
                mma16816(s[2*ng+1], qfh[kq][0],qfh[kq][1],qfh[kq][2],qfh[kq][3], kbl[1], kbl[3]);
                mma16816(s[2*ng+1], qfl[kq][0],qfl[kq][1],qfl[kq][2],qfl[kq][3], kbh[1], kbh[3]);
            }
        }

        // causal mask — only the two diagonal-overlapping k-tiles need it
        if (kt >= 2 * qt) {
            const int r0 = qt * 128 + (wid & 7) * 16 + (lane >> 2);
#pragma unroll
            for (int nt = 0; nt < 8; nt++)
#pragma unroll
                for (int e = 0; e < 4; e++) {
                    const int r  = r0 + (e >> 1) * 8;
                    const int cc = kt * 64 + nt * 8 + (lane & 3) * 2 + (e & 1);
                    if (cc > r) s[nt][e] = -1e9f;
                }
        }

#pragma unroll
        for (int h = 0; h < 2; h++) {
            float mt = -1e30f;
#pragma unroll
            for (int nt = 0; nt < 8; nt++)
                mt = fmaxf(mt, fmaxf(s[nt][h * 2], s[nt][h * 2 + 1]));
            mt = fmaxf(mt, __shfl_xor_sync(0xffffffffu, mt, 1));
            mt = fmaxf(mt, __shfl_xor_sync(0xffffffffu, mt, 2));
            const float mn = fmaxf(m_i[h], mt);
            float su = 0.f;
#pragma unroll
            for (int nt = 0; nt < 8; nt++) {
                s[nt][h * 2]     = __expf(s[nt][h * 2]     - mn);
                s[nt][h * 2 + 1] = __expf(s[nt][h * 2 + 1] - mn);
                su += s[nt][h * 2] + s[nt][h * 2 + 1];
            }
            su += __shfl_xor_sync(0xffffffffu, su, 1);
            su += __shfl_xor_sync(0xffffffffu, su, 2);
            const float alpha = __expf(m_i[h] - mn);
            l_i[h] = l_i[h] * alpha + su;
            m_i[h] = mn;
#pragma unroll
            for (int nt = 0; nt < 8; nt++) {
                o[nt][h * 2]     *= alpha;
                o[nt][h * 2 + 1] *= alpha;
            }
        }

#pragma unroll
        for (int kq = 0; kq < 4; kq++) {
            uint32_t pah[4], pal[4];
#pragma unroll
            for (int g = 0; g < 2; g++)
#pragma unroll
                for (int h = 0; h < 2; h++) {
                    const float p0 = s[2 * kq + g][h * 2];
                    const float p1 = s[2 * kq + g][h * 2 + 1];
                    const __nv_bfloat16 h0 = __float2bfloat16(p0);
                    const __nv_bfloat16 h1 = __float2bfloat16(p1);
                    const __nv_bfloat16 r0 = __float2bfloat16(p0 - __bfloat162float(h0));
                    const __nv_bfloat16 r1 = __float2bfloat16(p1 - __bfloat162float(h1));
                    pah[g * 2 + h] = pk(h0, h1);
                    pal[g * 2 + h] = pk(r0, r1);
                }
#pragma unroll
            for (int dg = 0; dg < 4; dg++) {
                const uint32_t rb = (uint32_t)(kq * 16 * APAD_B + dg * 32) + offV;
                uint32_t vbh[4], vbl[4];
                ldsm4t(vbh, sVh + rb);
                ldsm4t(vbl, sVl + rb);
                mma16816(o[2*dg],   pah[0],pah[1],pah[2],pah[3], vbh[0], vbh[2]);
                mma16816(o[2*dg],   pal[0],pal[1],pal[2],pal[3], vbh[0], vbh[2]);
                mma16816(o[2*dg],   pah[0],pah[1],pah[2],pah[3], vbl[0], vbl[2]);
                mma16816(o[2*dg+1], pah[0],pah[1],pah[2],pah[3], vbh[1], vbh[3]);
                mma16816(o[2*dg+1], pal[0],pal[1],pal[2],pal[3], vbh[1], vbh[3]);
                mma16816(o[2*dg+1], pah[0],pah[1],pah[2],pah[3], vbl[1], vbl[3]);
            }
        }
        __syncthreads();
        if (kt + 2 <= ktmax) issue(kt + 2);
    }

#pragma unroll
    for (int h = 0; h < 2; h++) {
        const float nv = 1.f / l_i[h];
        const int row = qt * 128 + wid * 16 + (lane >> 2) + h * 8;
#pragma unroll
        for (int nt = 0; nt < 8; nt++) {
            const int col = head * HS + nt * 8 + (lane & 3) * 2;
            const float v0 = o[nt][h * 2] * nv;
            const float v1 = o[nt][h * 2 + 1] * nv;
            const __nv_bfloat16 h0 = __float2bfloat16(v0), h1 = __float2bfloat16(v1);
            const __nv_bfloat16 l0 = __float2bfloat16(v0 - __bfloat162float(h0));
            const __nv_bfloat16 l1 = __float2bfloat16(v1 - __bfloat162float(h1));
            const size_t idx = (size_t)row * DIM + col;
            *(uint32_t*)&g_ah[idx] = pk(h0, h1);
            *(uint32_t*)&g_al[idx] = pk(l0, l1);
        }
    }
}

// ---------------------------------------------------------------------------
extern "C" void kernel_launch(void* const* d_in, const int* in_sizes, int n_in,
                              void* d_out, int out_size)
{
    const float* x  = (const float*)d_in[0];
    const float* wq = (const float*)d_in[1];
    const float* bq = (const float*)d_in[2];
    const float* wk = (const float*)d_in[3];
    const float* bk = (const float*)d_in[4];
    const float* wv = (const float*)d_in[5];
    const float* bv = (const float*)d_in[6];
    const float* wo = (const float*)d_in[7];
    const float* bo = (const float*)d_in[8];
    float* out = (float*)d_out;

    __nv_bfloat16 *xh,*xl,*ah,*al,*wqh,*wql,*wkh,*wkl,*wvh,*wvl,*woh,*wol;
    __nv_bfloat16 *qh,*ql,*kh,*kl,*vh,*vl;
    cudaGetSymbolAddress((void**)&xh,  g_xh);  cudaGetSymbolAddress((void**)&xl,  g_xl);
    cudaGetSymbolAddress((void**)&ah,  g_ah);  cudaGetSymbolAddress((void**)&al,  g_al);
    cudaGetSymbolAddress((void**)&wqh, g_wqh); cudaGetSymbolAddress((void**)&wql, g_wql);
    cudaGetSymbolAddress((void**)&wkh, g_wkh); cudaGetSymbolAddress((void**)&wkl, g_wkl);
    cudaGetSymbolAddress((void**)&wvh, g_wvh); cudaGetSymbolAddress((void**)&wvl, g_wvl);
    cudaGetSymbolAddress((void**)&woh, g_woh); cudaGetSymbolAddress((void**)&wol, g_wol);
    cudaGetSymbolAddress((void**)&qh,  g_qh);  cudaGetSymbolAddress((void**)&ql,  g_ql);
    cudaGetSymbolAddress((void**)&kh,  g_kh);  cudaGetSymbolAddress((void**)&kl,  g_kl);
    cudaGetSymbolAddress((void**)&vh,  g_vh);  cudaGetSymbolAddress((void**)&vl,  g_vl);

    cudaFuncSetAttribute(gemm_mma<0>, cudaFuncAttributeMaxDynamicSharedMemorySize, GEMM_SMEM);
    cudaFuncSetAttribute(gemm_mma<1>, cudaFuncAttributeMaxDynamicSharedMemorySize, GEMM_SMEM);
    cudaFuncSetAttribute(attn_mma,    cudaFuncAttributeMaxDynamicSharedMemorySize, ATT_SMEM);

    const int n4x = SEQ * DIM / 4, n4w = DIM * DIM / 4;
    conv_split<<<(n4x + 255) / 256, 256>>>(x,  xh,  xl,  n4x);
    conv_split<<<(n4w + 255) / 256, 256>>>(wq, wqh, wql, n4w);
    conv_split<<<(n4w + 255) / 256, 256>>>(wk, wkh, wkl, n4w);
    conv_split<<<(n4w + 255) / 256, 256>>>(wv, wvh, wvl, n4w);
    conv_split<<<(n4w + 255) / 256, 256>>>(wo, woh, wol, n4w);

    dim3 gg(DIM / 128, SEQ / 128);
    const float qscale = 0.125f;   // 1/sqrt(64), folded into Q projection
    gemm_mma<1><<<gg, 256, GEMM_SMEM>>>(xh, xl, wqh, wql, bq, qscale, qh, ql, nullptr);
    gemm_mma<1><<<gg, 256, GEMM_SMEM>>>(xh, xl, wkh, wkl, bk, 1.f,    kh, kl, nullptr);
    gemm_mma<1><<<gg, 256, GEMM_SMEM>>>(xh, xl, wvh, wvl, bv, 1.f,    vh, vl, nullptr);

    attn_mma<<<dim3(SEQ / 128, NH), 256, ATT_SMEM>>>();

    gemm_mma<0><<<gg, 256, GEMM_SMEM>>>(ah, al, woh, wol, bo, 1.f, nullptr, nullptr, out);
}